// round 9
// baseline (speedup 1.0000x reference)
#include <cuda_runtime.h>
#include <cuda_fp16.h>
#include <cstdint>

#define Bn   2048
#define Nin  512
#define Tn   100
#define H1n  512
#define H2n  256
#define On   5
#define Mn   (Tn*Bn)   // 204800 rows = (t,b)

// ---------------- scratch (device globals: allocation-free) ----------------
__device__ __half g_xh[(size_t)Mn * Nin];
__device__ __half g_xm[(size_t)Mn * Nin];
__device__ float  g_h1[(size_t)Mn * H1n];
__device__ __half g_s1[(size_t)Mn * H1n];
__device__ float  g_h2[(size_t)Mn * H2n];
__device__ __half g_s2[(size_t)Mn * H2n];
__device__ __half g_W1h[H1n * Nin], g_W1m[H1n * Nin];
__device__ __half g_W2h[H2n * H1n], g_W2m[H2n * H1n];

// ---------------- PTX helpers ----------------------------------------------
__device__ __forceinline__ uint32_t smem_u32(const void* p) {
    uint32_t a;
    asm("{ .reg .u64 t; cvta.to.shared.u64 t, %1; cvt.u32.u64 %0, t; }" : "=r"(a) : "l"(p));
    return a;
}
__device__ __forceinline__ void cp16(uint32_t dst, const void* src) {
    asm volatile("cp.async.cg.shared.global [%0], [%1], 16;" :: "r"(dst), "l"(src));
}
__device__ __forceinline__ void ldsm_x4(uint32_t& r0, uint32_t& r1, uint32_t& r2,
                                        uint32_t& r3, uint32_t addr) {
    asm volatile("ldmatrix.sync.aligned.m8n8.x4.shared.b16 {%0,%1,%2,%3}, [%4];"
                 : "=r"(r0), "=r"(r1), "=r"(r2), "=r"(r3) : "r"(addr));
}
__device__ __forceinline__ void mma16816(float& d0, float& d1, float& d2, float& d3,
                                         uint32_t a0, uint32_t a1, uint32_t a2, uint32_t a3,
                                         uint32_t b0, uint32_t b1) {
    asm volatile("mma.sync.aligned.m16n8k16.row.col.f32.f16.f16.f32 "
                 "{%0,%1,%2,%3}, {%4,%5,%6,%7}, {%8,%9}, {%0,%1,%2,%3};"
                 : "+f"(d0), "+f"(d1), "+f"(d2), "+f"(d3)
                 : "r"(a0), "r"(a1), "r"(a2), "r"(a3), "r"(b0), "r"(b1));
}

// ---------------- weight split: fp32 -> fp16 h/m ----------------------------
template <int MODE>
__global__ void k_wsplit(const float* __restrict__ src, int n) {
    int i = blockIdx.x * blockDim.x + threadIdx.x;
    if (i >= n) return;
    float v = src[i];
    __half h = __float2half_rn(v);
    __half m = __float2half_rn(v - __half2float(h));
    if (MODE == 1) { g_W1h[i] = h; g_W1m[i] = m; }
    else           { g_W2h[i] = h; g_W2m[i] = m; }
}

// ---------------- transpose + 2-split x (B,N,T) -> x{h,m}[(t*B+b)*N + n] ----
__global__ void k_transpose(const float* __restrict__ x) {
    __shared__ float tile[32][33];
    int b  = blockIdx.x;
    int n0 = blockIdx.y * 32;
    int t0 = blockIdx.z * 32;
    int tx = threadIdx.x, ty = threadIdx.y;   // 32 x 8
#pragma unroll
    for (int i = 0; i < 4; i++) {
        int n = n0 + ty + i * 8, t = t0 + tx;
        if (t < Tn) tile[ty + i * 8][tx] = x[((size_t)b * Nin + n) * Tn + t];
    }
    __syncthreads();
#pragma unroll
    for (int i = 0; i < 4; i++) {
        int t = t0 + ty + i * 8, n = n0 + tx;
        if (t < Tn) {
            float v = tile[tx][ty + i * 8];
            __half h = __float2half_rn(v);
            __half m = __float2half_rn(v - __half2float(h));
            size_t idx = ((size_t)t * Bn + b) * Nin + n;
            g_xh[idx] = h; g_xm[idx] = m;
        }
    }
}

// ---------------- fused multi-product HMMA GEMM -----------------------------
// MODE 1 (GEMM1): d = xh*W1h + xm*W1h + xh*W1m  -- all 3 products per k-chunk
// MODE 2 (GEMM2): d = s1*W2h + s1*W2m           -- shared A-fragment
// CTA tile 128x128, 2 M-tiles per CTA (grid.y halved), BK=32, 2-stage
// cp.async, SROW=40 padded smem, 8 warps (4M x 2N), warp tile 32x64.
#define SROW 40                         // fp16/row: 80B, 16B-aligned, no ldsm conflicts
#define TILE_BYTES (128 * SROW * 2)     // 10240 B per operand tile per stage

template <int NT, int MODE>
__global__ __launch_bounds__(256, 2) void k_gemm(const float* __restrict__ bias,
                                                 float* __restrict__ C) {
    constexpr int NTILES = (MODE == 1) ? 4 : 3;      // tiles per stage
    constexpr int STAGE  = NTILES * TILE_BYTES;
    constexpr int KC     = 16;                        // 512 / 32

    extern __shared__ __align__(16) char smem[];
    const uint32_t sb = smem_u32(smem);

    const int tid = threadIdx.x;
    const int wid = tid >> 5;
    const int lane = tid & 31;
    const int wm = wid >> 1;
    const int wn = wid & 1;
    const int n0 = blockIdx.x * 128;

    // loader: 512 16B-chunks per tile, 2 per thread
    const int lrow0 = tid >> 1;          // covers rows via q = tid + 256*j
    (void)lrow0;

    // ldsm per-lane fixed indices (same mapping as proven R5 kernel)
    const int arow0 = wm * 32 + (lane & 15);
    const int achk  = (lane >> 4) * 16;
    const int g     = lane >> 3;
    const int bchk  = (g & 1) * 16;
    const int brow_base = wn * 64 + (g >> 1) * 8 + (lane & 7);

    for (int half = 0; half < 2; half++) {
        const size_t m0 = ((size_t)blockIdx.y * 2 + half) * 128;

        float d[2][8][4];
#pragma unroll
        for (int i = 0; i < 2; i++)
#pragma unroll
            for (int j = 0; j < 8; j++)
#pragma unroll
                for (int k = 0; k < 4; k++) d[i][j][k] = 0.0f;

        auto do_loads = [&](int kc, int buf) {
            const int kb = kc * 32;
            const uint32_t st = sb + buf * STAGE;
            const __half* pl[4];
            int rowoff[4];
            if (MODE == 1) {
                pl[0] = g_xh;  rowoff[0] = 0;   // row base m0
                pl[1] = g_xm;  rowoff[1] = 0;
                pl[2] = g_W1h; rowoff[2] = 1;   // row base n0
                pl[3] = g_W1m; rowoff[3] = 1;
            } else {
                pl[0] = g_s1;  rowoff[0] = 0;
                pl[1] = g_W2h; rowoff[1] = 1;
                pl[2] = g_W2m; rowoff[2] = 1;
            }
#pragma unroll
            for (int t = 0; t < NTILES; t++) {
#pragma unroll
                for (int j = 0; j < 2; j++) {
                    int q = tid + 256 * j;
                    int row = q >> 2, ch = q & 3;
                    uint32_t dst = st + t * TILE_BYTES + row * (SROW * 2) + ch * 16;
                    const __half* src = pl[t] +
                        (rowoff[t] ? ((size_t)(n0 + row) * 512)
                                   : ((m0 + row) * 512)) + kb + ch * 8;
                    cp16(dst, src);
                }
            }
            asm volatile("cp.async.commit_group;");
        };

        do_loads(0, 0);
        asm volatile("cp.async.commit_group;");   // harmless empty group pad

        for (int kc = 0; kc < KC; kc++) {
            const int buf = kc & 1;
            if (kc + 1 < KC) {
                do_loads(kc + 1, buf ^ 1);
                asm volatile("cp.async.wait_group 1;");
            } else {
                asm volatile("cp.async.wait_group 0;");
            }
            __syncthreads();

            const uint32_t st = sb + buf * STAGE;
            const uint32_t tA0 = st;                                    // xh | s1
            const uint32_t tA1 = st + TILE_BYTES;                       // xm | W2h
            const uint32_t tB0 = st + (MODE == 1 ? 2 : 1) * TILE_BYTES; // W1h | W2h
            const uint32_t tB1 = st + (MODE == 1 ? 3 : 2) * TILE_BYTES; // W1m | W2m

#pragma unroll
            for (int ks = 0; ks < 2; ks++) {
                uint32_t a0[2][4];   // xh / s1 fragments
                uint32_t bb[4][4];
#pragma unroll
                for (int mt = 0; mt < 2; mt++) {
                    int row = arow0 + mt * 16;
                    ldsm_x4(a0[mt][0], a0[mt][1], a0[mt][2], a0[mt][3],
                            tA0 + (row * SROW + ks * 16) * 2 + achk);
                }
                // B = W*h plane
#pragma unroll
                for (int p = 0; p < 4; p++) {
                    int row = brow_base + p * 16;
                    ldsm_x4(bb[p][0], bb[p][1], bb[p][2], bb[p][3],
                            tB0 + (row * SROW + ks * 16) * 2 + bchk);
                }
#pragma unroll
                for (int mt = 0; mt < 2; mt++)
#pragma unroll
                    for (int nt = 0; nt < 8; nt++) {
                        int p = nt >> 1, s = nt & 1;
                        mma16816(d[mt][nt][0], d[mt][nt][1], d[mt][nt][2], d[mt][nt][3],
                                 a0[mt][0], a0[mt][1], a0[mt][2], a0[mt][3],
                                 bb[p][2 * s], bb[p][2 * s + 1]);
                    }
                if (MODE == 1) {
                    // second A plane (xm) x W1h
                    uint32_t a1[2][4];
#pragma unroll
                    for (int mt = 0; mt < 2; mt++) {
                        int row = arow0 + mt * 16;
                        ldsm_x4(a1[mt][0], a1[mt][1], a1[mt][2], a1[mt][3],
                                tA1 + (row * SROW + ks * 16) * 2 + achk);
                    }
#pragma unroll
                    for (int mt = 0; mt < 2; mt++)
#pragma unroll
                        for (int nt = 0; nt < 8; nt++) {
                            int p = nt >> 1, s = nt & 1;
                            mma16816(d[mt][nt][0], d[mt][nt][1], d[mt][nt][2], d[mt][nt][3],
                                     a1[mt][0], a1[mt][1], a1[mt][2], a1[mt][3],
                                     bb[p][2 * s], bb[p][2 * s + 1]);
                        }
                }
                // B = W*m plane (reuse bb regs), A = xh / s1
#pragma unroll
                for (int p = 0; p < 4; p++) {
                    int row = brow_base + p * 16;
                    ldsm_x4(bb[p][0], bb[p][1], bb[p][2], bb[p][3],
                            tB1 + (row * SROW + ks * 16) * 2 + bchk);
                }
#pragma unroll
                for (int mt = 0; mt < 2; mt++)
#pragma unroll
                    for (int nt = 0; nt < 8; nt++) {
                        int p = nt >> 1, s = nt & 1;
                        mma16816(d[mt][nt][0], d[mt][nt][1], d[mt][nt][2], d[mt][nt][3],
                                 a0[mt][0], a0[mt][1], a0[mt][2], a0[mt][3],
                                 bb[p][2 * s], bb[p][2 * s + 1]);
                    }
            }
            __syncthreads();
        }

        // epilogue: streaming stores (h buffers are consumed once by LIF)
        const int r = lane >> 2, c2 = (lane & 3) * 2;
#pragma unroll
        for (int mt = 0; mt < 2; mt++) {
#pragma unroll
            for (int nt = 0; nt < 8; nt++) {
                int n = n0 + wn * 64 + nt * 8 + c2;
                size_t m = m0 + wm * 32 + mt * 16 + r;
                float bx = bias[n], by = bias[n + 1];
                float2 o0 = { d[mt][nt][0] + bx, d[mt][nt][1] + by };
                float2 o1 = { d[mt][nt][2] + bx, d[mt][nt][3] + by };
                __stcs((float2*)(C + m * NT + n), o0);
                __stcs((float2*)(C + (m + 8) * NT + n), o1);
            }
        }
    }
}

// ---------------- LIF over time (h fp32 -> spikes fp16) ---------------------
template <int MODE>
__global__ void k_lif() {
    const float* h;
    __half* s;
    int width;
    if (MODE == 1) { h = g_h1; s = g_s1; width = H1n; }
    else           { h = g_h2; s = g_s2; width = H2n; }
    size_t g = (size_t)blockIdx.x * blockDim.x + threadIdx.x;
    if (g >= (size_t)Bn * width) return;
    const size_t step = (size_t)Bn * width;
    size_t idx = g;
    float v = 0.0f;
    const __half one = __float2half_rn(1.0f);
    const __half zero = __float2half_rn(0.0f);
#pragma unroll 4
    for (int t = 0; t < Tn; t++) {
        float hh = __ldcs(&h[idx]);
        v = v + (hh - v) * 0.5f;
        if (v - 1.0f >= 0.0f) { s[idx] = one; v = 0.0f; }
        else                  { s[idx] = zero; }
        idx += step;
    }
}

// ---------------- output layer: GEMM3 + LIF3 + time-reduce ------------------
__global__ void k_out(const float* __restrict__ Wo, const float* __restrict__ bo,
                      float* __restrict__ out) {
    int warp = (blockIdx.x * blockDim.x + threadIdx.x) >> 5;
    int lane = threadIdx.x & 31;
    if (warp >= Bn) return;
    int b = warp;

    float w[On][8];
#pragma unroll
    for (int k = 0; k < On; k++)
#pragma unroll
        for (int i = 0; i < 8; i++) w[k][i] = Wo[k * H2n + lane + 32 * i];
    float bol[On];
#pragma unroll
    for (int k = 0; k < On; k++) bol[k] = bo[k];

    float vo[On];
    int cnt[On];
#pragma unroll
    for (int k = 0; k < On; k++) { vo[k] = 0.0f; cnt[k] = 0; }

    for (int t = 0; t < Tn; t++) {
        const __half* s = g_s2 + ((size_t)t * Bn + b) * H2n;
        float sv[8];
#pragma unroll
        for (int i = 0; i < 8; i++) sv[i] = __half2float(s[lane + 32 * i]);
        float acc[On];
#pragma unroll
        for (int k = 0; k < On; k++) acc[k] = 0.0f;
#pragma unroll
        for (int i = 0; i < 8; i++)
#pragma unroll
            for (int k = 0; k < On; k++) acc[k] = fmaf(sv[i], w[k][i], acc[k]);
#pragma unroll
        for (int k = 0; k < On; k++) {
#pragma unroll
            for (int off = 16; off > 0; off >>= 1)
                acc[k] += __shfl_down_sync(0xffffffffu, acc[k], off);
        }
        if (lane == 0) {
#pragma unroll
            for (int k = 0; k < On; k++) {
                float o = acc[k] + bol[k];
                vo[k] = vo[k] + (o - vo[k]) * 0.5f;
                if (vo[k] - 1.0f >= 0.0f) { cnt[k]++; vo[k] = 0.0f; }
            }
        }
    }
    if (lane == 0) {
#pragma unroll
        for (int k = 0; k < On; k++)
            out[(size_t)b * On + k] = (float)cnt[k] / 100.0f;
    }
}

// ---------------------------------------------------------------------------
extern "C" void kernel_launch(void* const* d_in, const int* in_sizes, int n_in,
                              void* d_out, int out_size) {
    const float* x  = (const float*)d_in[0];   // (2048, 512, 100)
    const float* W1 = (const float*)d_in[1];   // (512, 512)
    const float* b1 = (const float*)d_in[2];   // (512)
    const float* W2 = (const float*)d_in[3];   // (256, 512)
    const float* b2 = (const float*)d_in[4];   // (256)
    const float* Wo = (const float*)d_in[5];   // (5, 256)
    const float* bo = (const float*)d_in[6];   // (5)
    float* out = (float*)d_out;                // (2048, 5)

    const int SMEM1 = 2 * 4 * TILE_BYTES;      // 81920
    const int SMEM2 = 2 * 3 * TILE_BYTES;      // 61440
    static bool attr_done = false;
    if (!attr_done) {
        cudaFuncSetAttribute(k_gemm<512, 1>, cudaFuncAttributeMaxDynamicSharedMemorySize, SMEM1);
        cudaFuncSetAttribute(k_gemm<256, 2>, cudaFuncAttributeMaxDynamicSharedMemorySize, SMEM2);
        attr_done = true;
    }

    // 0) 2-way fp16 splits of W1, W2
    k_wsplit<1><<<(H1n * Nin + 255) / 256, 256>>>(W1, H1n * Nin);
    k_wsplit<2><<<(H2n * H1n + 255) / 256, 256>>>(W2, H2n * H1n);
    // 1) transpose + 2-way fp16 split x
    k_transpose<<<dim3(Bn, Nin / 32, (Tn + 31) / 32), dim3(32, 8)>>>(x);
    // 2) h1 = x @ W1^T + b1 (fused 3-product single pass; 2 m-tiles/CTA)
    k_gemm<512, 1><<<dim3(H1n / 128, Mn / 256), 256, SMEM1>>>(b1, g_h1);
    // 3) LIF layer 1 -> s1 (fp16 spikes, exact)
    k_lif<1><<<(Bn * H1n) / 256, 256>>>();
    // 4) h2 = s1 @ W2^T + b2 (fused 2-product single pass; 2 m-tiles/CTA)
    k_gemm<256, 2><<<dim3(H2n / 128, Mn / 256), 256, SMEM2>>>(b2, g_h2);
    // 5) LIF layer 2 -> s2
    k_lif<2><<<(Bn * H2n) / 256, 256>>>();
    // 6) output layer GEMM + LIF + spike-count reduce
    k_out<<<Bn / 8, 256>>>(Wo, bo, out);
}